// round 5
// baseline (speedup 1.0000x reference)
#include <cuda_runtime.h>

#define NN 131072
#define GG 4096
#define EE 1048576
#define SS 64
#define HH 128

// Scratch (no allocations allowed). 16B-aligned: read/written as float4/v4-red.
__device__ __align__(16) float g_w_src[2][SS];     // W @ att_src per branch
__device__ __align__(16) float g_w_dst[2][SS];     // W @ att_dst per branch
__device__ __align__(16) float g_a_dstv[2][GG];    // a_dst at self node of each graph
__device__ __align__(16) float g_acc[2][GG * SS];  // sum of p * x[src] per graph (S-space)
__device__ __align__(16) float g_denom[2][GG];     // sum of p per graph

// -------------------------------------------------------------------------
// Zero accumulators
__global__ void zero_kernel() {
    int i = blockIdx.x * blockDim.x + threadIdx.x;
    if (i < 2 * GG * SS) ((float*)g_acc)[i] = 0.0f;
    if (i < 2 * GG) ((float*)g_denom)[i] = 0.0f;
}

// -------------------------------------------------------------------------
// w_src = W @ att_src, w_dst = W @ att_dst for both branches (256 threads)
__global__ void prep_kernel(const float* __restrict__ upW,
                            const float* __restrict__ upAs,
                            const float* __restrict__ upAd,
                            const float* __restrict__ dnW,
                            const float* __restrict__ dnAs,
                            const float* __restrict__ dnAd) {
    int t = threadIdx.x;           // 256 threads
    int combo = t >> 6;            // 0:up/src 1:up/dst 2:dn/src 3:dn/dst
    int s = t & 63;
    const float* W = (combo < 2) ? upW : dnW;
    const float* a = (combo == 0) ? upAs : (combo == 1) ? upAd
                    : (combo == 2) ? dnAs : dnAd;
    float sum = 0.0f;
#pragma unroll 8
    for (int h = 0; h < HH; ++h) sum += W[s * HH + h] * a[h];
    float* dstp = (combo == 0) ? g_w_src[0] : (combo == 1) ? g_w_dst[0]
                 : (combo == 2) ? g_w_src[1] : g_w_dst[1];
    dstp[s] = sum;
}

// -------------------------------------------------------------------------
// a_dst for the self node (node 32g+31) of every graph, both branches.
// One warp per (branch, graph).
__global__ void dstval_kernel(const float* __restrict__ up_x,
                              const float* __restrict__ dn_x) {
    int wid = (blockIdx.x * blockDim.x + threadIdx.x) >> 5;
    int lane = threadIdx.x & 31;
    if (wid >= 2 * GG) return;
    int branch = wid & 1;
    int g = wid >> 1;
    const float* x = branch ? dn_x : up_x;
    int node = g * 32 + 31;
    float2 xv = *(const float2*)(x + (size_t)node * SS + lane * 2);
    float2 wv = *(const float2*)(&g_w_dst[branch][lane * 2]);
    float s = xv.x * wv.x + xv.y * wv.y;
#pragma unroll
    for (int o = 16; o; o >>= 1) s += __shfl_xor_sync(0xffffffffu, s, o);
    if (lane == 0) g_a_dstv[branch][g] = s;
}

// -------------------------------------------------------------------------
// Single edge pass. edge_index is INT32 (JAX x64 disabled: astype(int64) is a
// no-op to int32). Only edges with dst%32==31 matter (~1/32). For those:
//   e  = leaky_relu(x[src].w_src + a_dst[g]),  p = exp(e)      (no max: safe)
//   acc[g][:] += p * x[src][:],  denom[g] += p
// The x[src] row gather serves BOTH the attention dot and the accumulation.
// Warp-cooperative: ballot compacts relevant edges; 16 lanes handle the
// 64-float row as float4s; scatter via red.global.add.v4.f32.
__global__ void edge_kernel(const int* __restrict__ up_ei,
                            const int* __restrict__ dn_ei,
                            const float* __restrict__ up_x,
                            const float* __restrict__ dn_x) {
    int branch = blockIdx.y;
    const int* ei = branch ? dn_ei : up_ei;
    const float* x = branch ? dn_x : up_x;
    float* acc = g_acc[branch];
    float* denom = g_denom[branch];
    const float* adst = g_a_dstv[branch];
    int lane = threadIdx.x & 31;

    // each lane holds its float4 chunk of w_src (mirrored in upper half-warp)
    float4 wv = *(const float4*)(&g_w_src[branch][(lane & 15) * 4]);

    int e = blockIdx.x * blockDim.x + threadIdx.x;
    int src = 0, gph = 0;
    bool rel = false;
    if (e < EE) {
        int d = ei[EE + e];                      // coalesced dst stream (int32)
        if ((d & 31) == 31) {
            rel = true;
            gph = d >> 5;
            src = ei[e];                         // lazy src load (rare)
        }
    }
    unsigned mask = __ballot_sync(0xffffffffu, rel);
    while (mask) {
        int l = __ffs(mask) - 1;
        mask &= mask - 1;
        int s2 = __shfl_sync(0xffffffffu, src, l);
        int g2 = __shfl_sync(0xffffffffu, gph, l);
        // gather x[src] row: lanes 0-15 cover 64 floats; upper half mirrors
        float4 v = *(const float4*)(x + (size_t)s2 * SS + (lane & 15) * 4);
        float part = v.x * wv.x + v.y * wv.y + v.z * wv.z + v.w * wv.w;
#pragma unroll
        for (int o = 8; o; o >>= 1)
            part += __shfl_xor_sync(0xffffffffu, part, o);   // sum within 16-group
        float ev = part + adst[g2];
        ev = ev > 0.0f ? ev : 0.2f * ev;          // leaky_relu(0.2)
        float p = __expf(ev);                     // no max-shift needed (|ev|<~12)
        if (lane < 16) {
            float* addr = acc + g2 * SS + lane * 4;
            float4 pv = make_float4(v.x * p, v.y * p, v.z * p, v.w * p);
            asm volatile("red.global.add.v4.f32 [%0], {%1,%2,%3,%4};"
                         :: "l"(addr), "f"(pv.x), "f"(pv.y), "f"(pv.z), "f"(pv.w)
                         : "memory");
        } else if (lane == 16) {
            atomicAdd(denom + g2, p);
        }
    }
}

// -------------------------------------------------------------------------
// Epilogue: per graph g:
//   v_b = acc_b[g]/(denom_b[g]+1e-16)          (S=64)
//   h_b = sigmoid(v_b @ W_b + bias_b)          (H=128)
//   out[g] = (h_up * h_dn) . mlpW + mlpb
// 256 threads/block: thread t -> (branch t>>7, column t&127). W stays in L1.
__global__ void final_kernel(const float* __restrict__ upW,
                             const float* __restrict__ dnW,
                             const float* __restrict__ upB,
                             const float* __restrict__ dnB,
                             const float* __restrict__ mlpW,
                             const float* __restrict__ mlpB,
                             float* __restrict__ out) {
    __shared__ float vsh[2][SS];
    __shared__ float hsh[2][HH];
    __shared__ float red[4];
    int t = threadIdx.x;
    int b = t >> 7, c = t & 127;
    const float* W = b ? dnW : upW;
    const float* bias = b ? dnB : upB;
    float mb = mlpB[0];

    for (int g = blockIdx.x; g < GG; g += gridDim.x) {
        if (t < 128) {
            int bb = t >> 6, s = t & 63;
            float dn = g_denom[bb][g];
            vsh[bb][s] = g_acc[bb][g * SS + s] / (dn + 1e-16f);
        }
        __syncthreads();
        float sum = 0.0f;
#pragma unroll 8
        for (int s = 0; s < SS; ++s) sum += vsh[b][s] * W[s * HH + c];
        sum += bias[c];
        hsh[b][c] = 1.0f / (1.0f + __expf(-sum));
        __syncthreads();
        if (t < 128) {
            float pr = hsh[0][t] * hsh[1][t] * mlpW[t];
#pragma unroll
            for (int o = 16; o; o >>= 1)
                pr += __shfl_xor_sync(0xffffffffu, pr, o);
            if ((t & 31) == 0) red[t >> 5] = pr;
        }
        __syncthreads();
        if (t == 0) out[g] = red[0] + red[1] + red[2] + red[3] + mb;
        __syncthreads();
    }
}

// -------------------------------------------------------------------------
extern "C" void kernel_launch(void* const* d_in, const int* in_sizes, int n_in,
                              void* d_out, int out_size) {
    const float* up_x  = (const float*)d_in[0];
    const int*   up_ei = (const int*)d_in[1];
    const float* dn_x  = (const float*)d_in[3];
    const int*   dn_ei = (const int*)d_in[4];
    const float* upW   = (const float*)d_in[6];
    const float* upAs  = (const float*)d_in[7];
    const float* upAd  = (const float*)d_in[8];
    const float* upB   = (const float*)d_in[9];
    const float* dnW   = (const float*)d_in[10];
    const float* dnAs  = (const float*)d_in[11];
    const float* dnAd  = (const float*)d_in[12];
    const float* dnB   = (const float*)d_in[13];
    const float* mlpW  = (const float*)d_in[14];
    const float* mlpB  = (const float*)d_in[15];
    float* out = (float*)d_out;

    zero_kernel<<<2048, 256>>>();
    prep_kernel<<<1, 256>>>(upW, upAs, upAd, dnW, dnAs, dnAd);
    dstval_kernel<<<1024, 256>>>(up_x, dn_x);
    dim3 egrid(EE / 256, 2);
    edge_kernel<<<egrid, 256>>>(up_ei, dn_ei, up_x, dn_x);
    final_kernel<<<256, 256>>>(upW, dnW, upB, dnB, mlpW, mlpB, out);
}